// round 17
// baseline (speedup 1.0000x reference)
#include <cuda_runtime.h>
#include <cuda_fp16.h>
#include <cstdint>
#include <cstddef>

// m16n8k16 row.col f32.f16.f16.f32 (family-common PTX, works on plain sm_103)
#define MMA_F16(c, a, b0, b1)                                                   \
    asm volatile("mma.sync.aligned.m16n8k16.row.col.f32.f16.f16.f32 "           \
                 "{%0,%1,%2,%3},{%4,%5,%6,%7},{%8,%9},{%0,%1,%2,%3};"           \
                 : "+f"((c)[0]), "+f"((c)[1]), "+f"((c)[2]), "+f"((c)[3])       \
                 : "r"((a)[0]), "r"((a)[1]), "r"((a)[2]), "r"((a)[3]),          \
                   "r"(b0), "r"(b1))

// ---------------- problem constants ----------------
static constexpr int BATCH = 16;
static constexpr int C     = 64;     // CIN == COUT
static constexpr int HW    = 112;
static constexpr int TH    = 8;      // tile h  -> M = 128 pixels per CTA
static constexpr int TW    = 16;     // tile w

// halo: 32 channel-pairs x 10 rows x 18 cols of half2 words
static constexpr int PRS   = 20;     // row stride in words (half2)
static constexpr int PPL   = 200;    // pair-plane stride in words; 200 % 32 == 8 -> conflict-free

// fragment-ordered fp16 weights: 144 chunks x 512 B = 73728 B (18432 words)
// chunk = (kpos*4 + s)*4 + wn ; word-in-chunk = lane*4 + (nt*2 + j)
__device__ uint32_t g_B2[18432];

// ---- prep kernel: wt[fp32, (cin*9+kpos) x 64] -> fragment-ordered fp16 pairs ----
__global__ void __launch_bounds__(256, 1)
prep_weights(const float* __restrict__ wt)
{
    int idx    = blockIdx.x * 256 + threadIdx.x;   // 0..18431
    int chunk  = idx >> 7;                          // 0..143
    int within = idx & 127;
    int lane = within >> 2, r = within & 3;
    int nt = r >> 1;
    int j  = r & 1;
    int wn   = chunk & 3;
    int s    = (chunk >> 2) & 3;
    int kpos = chunk >> 4;                          // 0..8 (exact)
    int g = lane >> 2, t = lane & 3;
    int co  = wn * 16 + nt * 8 + g;
    int cin = s * 16 + 2 * t + 8 * j;
    __half lo = __float2half_rn(wt[((size_t)cin * 9 + kpos) * 64 + co]);
    __half hi = __float2half_rn(wt[((size_t)(cin + 1) * 9 + kpos) * 64 + co]);
    __half2 v = __halves2half2(lo, hi);
    g_B2[idx] = *(uint32_t*)&v;
}

__global__ void __launch_bounds__(256, 3)
conv3x3_f16_mma(const float* __restrict__ x,
                const float* __restrict__ bias,
                float* __restrict__ out)
{
    __shared__ uint32_t halo32[32 * PPL];           // 6400 words = 25600 B
    __half* haloh = (__half*)halo32;

    const int tid  = threadIdx.x;
    const int lane = tid & 31;
    const int wid  = tid >> 5;
    const int wm   = wid >> 2;          // 0..1 : 4 h-rows each
    const int wn   = wid & 3;           // 0..3 : 16 couts each
    const int g    = lane >> 2;         // groupID 0..7
    const int t    = lane & 3;          // thread-in-group

    const int w0 = blockIdx.x * TW;
    const int h0 = blockIdx.y * TH;
    const int b  = blockIdx.z;

    // ---- halo load: 64 cin x 10 x 18 -> fp16 channel-pair layout, zero padded ----
    #pragma unroll 5
    for (int i = 0; i < 45; ++i) {      // 45*256 == 64*10*18 exactly
        int idx = tid + i * 256;
        int c   = idx / 180;
        int rem = idx - c * 180;
        int r   = rem / 18;
        int w   = rem - r * 18;
        int gh = h0 - 1 + r, gw = w0 - 1 + w;
        float v = 0.f;
        if ((unsigned)gh < (unsigned)HW && (unsigned)gw < (unsigned)HW)
            v = x[(((size_t)b * C + c) * HW + gh) * HW + gw];
        haloh[(c >> 1) * (2 * PPL) + r * (2 * PRS) + 2 * w + (c & 1)] = __float2half_rn(v);
    }
    __syncthreads();

    float acc[4][2][4];                 // [mt][nt][creg]
    #pragma unroll
    for (int i = 0; i < 4; ++i)
        #pragma unroll
        for (int j = 0; j < 2; ++j)
            #pragma unroll
            for (int k = 0; k < 4; ++k) acc[i][j][k] = 0.f;

    const uint4* bq = (const uint4*)g_B2 + wn * 32 + lane;
    const uint32_t* awb = halo32 + t * PPL + (wm * 4) * PRS + g;

    // FULLY UNROLLED: s -> kw -> kh. kh-factored A rows: d = mt + kh (0..5).
    // Per kh: ONE LDG.128 (nt=2) feeds 8 MMAs.
    #pragma unroll
    for (int s = 0; s < 4; ++s) {
        #pragma unroll
        for (int kw = 0; kw < 3; ++kw) {
            const uint32_t* p = awb + s * 8 * PPL + kw;
            // A[d]: halo row wm*4 + d, both w-halves, both K-half pairs
            uint32_t A[6][4];
            #pragma unroll
            for (int d = 0; d < 6; ++d) {
                A[d][0] = p[d * PRS];                // pair t,   w=g
                A[d][1] = p[d * PRS + 8];            // pair t,   w=g+8
                A[d][2] = p[d * PRS + 4 * PPL];      // pair t+4, w=g
                A[d][3] = p[d * PRS + 4 * PPL + 8];  // pair t+4, w=g+8
            }
            #pragma unroll
            for (int kh = 0; kh < 3; ++kh) {
                const int kpos = kh * 3 + kw;
                uint32_t Bf[4];
                *(uint4*)&Bf[0] = __ldg(bq + (kpos * 4 + s) * 128);

                #pragma unroll
                for (int mt = 0; mt < 4; ++mt)
                    #pragma unroll
                    for (int nt = 0; nt < 2; ++nt)
                        MMA_F16(acc[mt][nt], A[mt + kh], Bf[2 * nt], Bf[2 * nt + 1]);
            }
        }
    }

    // ---- epilogue ----
    #pragma unroll
    for (int nt = 0; nt < 2; ++nt) {
        const int co0 = wn * 16 + nt * 8 + 2 * t;
        const float bz0 = __ldg(bias + co0);
        const float bz1 = __ldg(bias + co0 + 1);
        #pragma unroll
        for (int mt = 0; mt < 4; ++mt) {
            const int h = h0 + wm * 4 + mt;
            float* p0 = out + (((size_t)b * C + co0) * HW + h) * HW + w0;
            float* p1 = p0 + (size_t)HW * HW;
            p0[g]     = acc[mt][nt][0] + bz0;   // w=g,   cout co0
            p1[g]     = acc[mt][nt][1] + bz1;   // w=g,   cout co0+1
            p0[g + 8] = acc[mt][nt][2] + bz0;   // w=g+8, cout co0
            p1[g + 8] = acc[mt][nt][3] + bz1;   // w=g+8, cout co0+1
        }
    }
}

extern "C" void kernel_launch(void* const* d_in, const int* in_sizes, int n_in,
                              void* d_out, int out_size)
{
    const float* x    = (const float*)d_in[0];
    const float* wt   = (const float*)d_in[1];
    const float* bias = (const float*)d_in[2];
    float* out = (float*)d_out;

    prep_weights<<<72, 256>>>(wt);      // 72*256 == 18432 exactly

    dim3 grid(HW / TW, HW / TH, BATCH);   // 7 x 14 x 16
    conv3x3_f16_mma<<<grid, 256>>>(x, bias, out);
}